// round 12
// baseline (speedup 1.0000x reference)
#include <cuda_runtime.h>
#include <cuda_bf16.h>
#include <cuda_fp16.h>
#include <math.h>
#include <stdint.h>

#define NHEADS 16
#define HDIM 128
#define TSEQ 2048
#define BATCH 4
#define HMODEL 2048
#define MROWS (BATCH*TSEQ)   // 8192

// ---------------- scratch (device globals: allocation-free) ----------------
__device__ float g_cos[TSEQ*64];
__device__ float g_sin[TSEQ*64];
// fp16 operands for projection GEMMs (A single, B hi/lo)
__device__ __half g_xh[(size_t)MROWS*HMODEL];
__device__ __half g_wh[4][(size_t)HMODEL*HMODEL];   // q,k,v,o contiguous
__device__ __half g_wl[4][(size_t)HMODEL*HMODEL];
__device__ __half g_aoh[(size_t)MROWS*HMODEL];
// bf16 hi/lo q,k,v for flash (post-RoPE), written by QKV GEMM epilogue
__device__ __nv_bfloat16 g_qhi[(size_t)BATCH*NHEADS*TSEQ*HDIM];
__device__ __nv_bfloat16 g_qlo[(size_t)BATCH*NHEADS*TSEQ*HDIM];
__device__ __nv_bfloat16 g_khi[(size_t)BATCH*NHEADS*TSEQ*HDIM];
__device__ __nv_bfloat16 g_klo[(size_t)BATCH*NHEADS*TSEQ*HDIM];
__device__ __nv_bfloat16 g_vhi[(size_t)BATCH*NHEADS*TSEQ*HDIM];
__device__ __nv_bfloat16 g_vlo[(size_t)BATCH*NHEADS*TSEQ*HDIM];

// ================= PTX helpers (baseline ISA only) ==========================
__device__ __forceinline__ uint32_t smem_u32(const void* p) {
    uint32_t a;
    asm("{ .reg .u64 t; cvta.to.shared.u64 t, %1; cvt.u32.u64 %0, t; }" : "=r"(a) : "l"(p));
    return a;
}
__device__ __forceinline__ void cp16(uint32_t dst, const void* src) {
    asm volatile("cp.async.cg.shared.global [%0], [%1], 16;" :: "r"(dst), "l"(src));
}
#define CP_COMMIT() asm volatile("cp.async.commit_group;" ::: "memory")
#define CP_WAIT(n)  asm volatile("cp.async.wait_group %0;" :: "n"(n) : "memory")

#define LDMX4(r, addr) \
    asm volatile("ldmatrix.sync.aligned.m8n8.x4.shared.b16 {%0,%1,%2,%3}, [%4];" \
        : "=r"((r)[0]), "=r"((r)[1]), "=r"((r)[2]), "=r"((r)[3]) : "r"(addr))
#define LDMX4T(r, addr) \
    asm volatile("ldmatrix.sync.aligned.m8n8.x4.trans.shared.b16 {%0,%1,%2,%3}, [%4];" \
        : "=r"((r)[0]), "=r"((r)[1]), "=r"((r)[2]), "=r"((r)[3]) : "r"(addr))

#define MMA16816(c, a, b) \
    asm volatile("mma.sync.aligned.m16n8k16.row.col.f32.bf16.bf16.f32 " \
        "{%0,%1,%2,%3}, {%4,%5,%6,%7}, {%8,%9}, {%0,%1,%2,%3};" \
        : "+f"((c)[0]), "+f"((c)[1]), "+f"((c)[2]), "+f"((c)[3]) \
        : "r"((a)[0]), "r"((a)[1]), "r"((a)[2]), "r"((a)[3]), "r"((b)[0]), "r"((b)[1]))

#define MMAF16(c, a, b) \
    asm volatile("mma.sync.aligned.m16n8k16.row.col.f32.f16.f16.f32 " \
        "{%0,%1,%2,%3}, {%4,%5,%6,%7}, {%8,%9}, {%0,%1,%2,%3};" \
        : "+f"((c)[0]), "+f"((c)[1]), "+f"((c)[2]), "+f"((c)[3]) \
        : "r"((a)[0]), "r"((a)[1]), "r"((a)[2]), "r"((a)[3]), "r"((b)[0]), "r"((b)[1]))

// ---------------- fp32 -> fp16 single convert (x) -----------------------------
__global__ void tofp16_kernel(const float* __restrict__ src,
                              __half* __restrict__ dst, int n4) {
    int i = blockIdx.x * blockDim.x + threadIdx.x;
    if (i >= n4) return;
    float4 v = ((const float4*)src)[i];
    ((__half2*)dst)[2*i]   = __floats2half2_rn(v.x, v.y);
    ((__half2*)dst)[2*i+1] = __floats2half2_rn(v.z, v.w);
}

// ---- fused 4-matrix W split to fp16 hi/lo (one launch) ----
__global__ void split_w_kernel(const float* __restrict__ w0, const float* __restrict__ w1,
                               const float* __restrict__ w2, const float* __restrict__ w3) {
    const float* srcs[4] = {w0, w1, w2, w3};
    int m = blockIdx.y;
    const float* src = srcs[m];
    __half* hi = g_wh[m];
    __half* lo = g_wl[m];
    int i = blockIdx.x * blockDim.x + threadIdx.x;
    float4 v = ((const float4*)src)[i];
    float vs[4] = {v.x, v.y, v.z, v.w};
    __half h[4], l[4];
    #pragma unroll
    for (int j = 0; j < 4; j++) {
        h[j] = __float2half(vs[j]);
        l[j] = __float2half(vs[j] - __half2float(h[j]));
    }
    __half2 h0; h0.x = h[0]; h0.y = h[1];
    __half2 h1; h1.x = h[2]; h1.y = h[3];
    __half2 l0; l0.x = l[0]; l0.y = l[1];
    __half2 l1; l1.x = l[2]; l1.y = l[3];
    ((__half2*)hi)[2*i]   = h0;
    ((__half2*)hi)[2*i+1] = h1;
    ((__half2*)lo)[2*i]   = l0;
    ((__half2*)lo)[2*i+1] = l1;
}

// ---------------- RoPE table -------------------------------------------------
__global__ void rope_table_kernel() {
    int i = blockIdx.x * blockDim.x + threadIdx.x;
    if (i >= TSEQ * 64) return;
    int t = i >> 6, d = i & 63;
    double inv = exp(-((double)(2 * d) / 128.0) * log(10000.0));
    double ang = (double)t * inv;
    double s, c;
    sincos(ang, &s, &c);
    g_cos[i] = (float)c;
    g_sin[i] = (float)s;
}

// ================= warp-mma fp16 2-pass GEMM (occ=2, 2-stage BK32) ===========
// C[m,n] = sum_k A[m,k]*B[n,k];  A single fp16, B fp16 hi/lo: C = A*Bh + A*Bl.
// MODE 0: C fp32 row-major [M,2048]. MODE 1: fused QKV with RoPE + bf16 split
//         epilogue into g_{q,k,v}{hi,lo}.
#define ROWB 80
#define PART (128 * ROWB)          // 10240
#define STG  (3 * PART)            // 30720 per stage (A, Bh, Bl)
#define NSTG 2
#define TILEPAD 130
#define GEMM_SMEM 66560            // max(2*STG=61440, 128*130*4=66560)

template<int MODE>
__global__ void __launch_bounds__(256, 2)
tc_gemm_kernel(const __half* __restrict__ A,
               const __half* __restrict__ Bhi, const __half* __restrict__ Blo,
               float* __restrict__ C0)
{
    extern __shared__ char smem[];
    const uint32_t sb = smem_u32(smem);
    const int tid = threadIdx.x;
    const int lane = tid & 31, w = tid >> 5;
    const int wm = w & 1, wn = w >> 1;

    const __half* aP = A   + (size_t)blockIdx.y * 128 * HMODEL;
    const __half* bH = Bhi + (size_t)blockIdx.x * 128 * HMODEL;
    const __half* bL = Blo + (size_t)blockIdx.x * 128 * HMODEL;

    const int c0 = tid, c1 = tid + 256;
    const int r0 = c0 >> 2, q0 = c0 & 3;
    const int r1 = c1 >> 2, q1 = c1 & 3;

    auto load_stage = [&](int s, int kc) {
        uint32_t base = sb + s * STG;
        size_t g0 = (size_t)r0 * HMODEL + kc * 32 + q0 * 8;
        size_t g1 = (size_t)r1 * HMODEL + kc * 32 + q1 * 8;
        uint32_t d0 = base + r0 * ROWB + q0 * 16;
        uint32_t d1 = base + r1 * ROWB + q1 * 16;
        cp16(d0,            aP + g0);  cp16(d1,            aP + g1);
        cp16(d0 + PART,     bH + g0);  cp16(d1 + PART,     bH + g1);
        cp16(d0 + 2*PART,   bL + g0);  cp16(d1 + 2*PART,   bL + g1);
    };

    float acc[4][4][4];
    #pragma unroll
    for (int i = 0; i < 4; i++)
        #pragma unroll
        for (int j = 0; j < 4; j++)
            #pragma unroll
            for (int e = 0; e < 4; e++) acc[i][j][e] = 0.f;

    load_stage(0, 0); CP_COMMIT();
    load_stage(1, 1); CP_COMMIT();

    const int NKC = HMODEL / 32;   // 64
    for (int kc = 0; kc < NKC; kc++) {
        CP_WAIT(1);
        __syncthreads();
        uint32_t stage = sb + (kc & 1) * STG;

        #pragma unroll
        for (int step = 0; step < 2; step++) {
            uint32_t bhi[4][2], blo[4][2];
            const int qd = lane >> 3;
            #pragma unroll
            for (int nt2 = 0; nt2 < 2; nt2++) {
                uint32_t brow = wn * 32 + nt2 * 16 + (qd >> 1) * 8 + (lane & 7);
                uint32_t bd = stage + PART + brow * ROWB + step * 32 + (qd & 1) * 16;
                uint32_t th[4], tl[4];
                LDMX4(th, bd);
                LDMX4(tl, bd + PART);
                bhi[nt2*2][0] = th[0]; bhi[nt2*2][1] = th[1];
                bhi[nt2*2+1][0] = th[2]; bhi[nt2*2+1][1] = th[3];
                blo[nt2*2][0] = tl[0]; blo[nt2*2][1] = tl[1];
                blo[nt2*2+1][0] = tl[2]; blo[nt2*2+1][1] = tl[3];
            }
            #pragma unroll
            for (int mt = 0; mt < 4; mt++) {
                uint32_t ah[4];
                uint32_t arow = wm * 64 + mt * 16 + (lane & 15);
                uint32_t ad = stage + arow * ROWB + step * 32 + (lane >> 4) * 16;
                LDMX4(ah, ad);
                #pragma unroll
                for (int nt = 0; nt < 4; nt++) MMAF16(acc[mt][nt], ah, bhi[nt]);
                #pragma unroll
                for (int nt = 0; nt < 4; nt++) MMAF16(acc[mt][nt], ah, blo[nt]);
            }
        }
        __syncthreads();
        if (kc + 2 < NKC) load_stage(kc & 1, kc + 2);
        CP_COMMIT();
    }

    if (MODE == 0) {
        #pragma unroll
        for (int mt = 0; mt < 4; mt++) {
            int mrow = blockIdx.y * 128 + wm * 64 + mt * 16 + (lane >> 2);
            #pragma unroll
            for (int nt = 0; nt < 4; nt++) {
                int n = blockIdx.x * 128 + wn * 32 + nt * 8 + (lane & 3) * 2;
                float* dst = C0 + (size_t)mrow * HMODEL + n;
                *(float2*)dst = make_float2(acc[mt][nt][0], acc[mt][nt][1]);
                *(float2*)(dst + 8 * HMODEL) = make_float2(acc[mt][nt][2], acc[mt][nt][3]);
            }
        }
    } else {
        float* tile = (float*)smem;   // [128][TILEPAD]
        #pragma unroll
        for (int mt = 0; mt < 4; mt++) {
            int rl = wm * 64 + mt * 16 + (lane >> 2);
            #pragma unroll
            for (int nt = 0; nt < 4; nt++) {
                int cl = wn * 32 + nt * 8 + (lane & 3) * 2;
                tile[rl * TILEPAD + cl]       = acc[mt][nt][0];
                tile[rl * TILEPAD + cl + 1]   = acc[mt][nt][1];
                tile[(rl + 8) * TILEPAD + cl]     = acc[mt][nt][2];
                tile[(rl + 8) * TILEPAD + cl + 1] = acc[mt][nt][3];
            }
        }
        __syncthreads();

        const int matrix = blockIdx.x >> 4;     // 0:q 1:k 2:v
        const int head   = blockIdx.x & 15;
        __nv_bfloat16* hi = (matrix == 0) ? g_qhi : (matrix == 1) ? g_khi : g_vhi;
        __nv_bfloat16* lo = (matrix == 0) ? g_qlo : (matrix == 1) ? g_klo : g_vlo;
        const bool dorope = (matrix < 2);

        #pragma unroll
        for (int it = 0; it < 16; it++) {
            int idx = tid + it * 256;
            int rl = idx >> 5;
            int dp = (idx & 31) * 2;
            int mrow = blockIdx.y * 128 + rl;
            int b = mrow >> 11, t = mrow & (TSEQ - 1);
            float x0a = tile[rl * TILEPAD + dp];
            float x0b = tile[rl * TILEPAD + dp + 1];
            float x1a = tile[rl * TILEPAD + dp + 64];
            float x1b = tile[rl * TILEPAD + dp + 65];
            float y0a, y0b, y1a, y1b;
            if (dorope) {
                float c0 = g_cos[t * 64 + dp],     s0 = g_sin[t * 64 + dp];
                float c1 = g_cos[t * 64 + dp + 1], s1 = g_sin[t * 64 + dp + 1];
                y0a = x0a * c0 - x1a * s0;  y1a = x1a * c0 + x0a * s0;
                y0b = x0b * c1 - x1b * s1;  y1b = x1b * c1 + x0b * s1;
            } else {
                y0a = x0a; y0b = x0b; y1a = x1a; y1b = x1b;
            }
            size_t base = ((size_t)(b * NHEADS + head) * TSEQ + t) * HDIM;
            __nv_bfloat16 h0a = __float2bfloat16(y0a), h0b = __float2bfloat16(y0b);
            __nv_bfloat16 h1a = __float2bfloat16(y1a), h1b = __float2bfloat16(y1b);
            __nv_bfloat162 hv0; hv0.x = h0a; hv0.y = h0b;
            __nv_bfloat162 hv1; hv1.x = h1a; hv1.y = h1b;
            __nv_bfloat162 lv0, lv1;
            lv0.x = __float2bfloat16(y0a - __bfloat162float(h0a));
            lv0.y = __float2bfloat16(y0b - __bfloat162float(h0b));
            lv1.x = __float2bfloat16(y1a - __bfloat162float(h1a));
            lv1.y = __float2bfloat16(y1b - __bfloat162float(h1b));
            *(__nv_bfloat162*)(hi + base + dp)      = hv0;
            *(__nv_bfloat162*)(hi + base + dp + 64) = hv1;
            *(__nv_bfloat162*)(lo + base + dp)      = lv0;
            *(__nv_bfloat162*)(lo + base + dp + 64) = lv1;
        }
    }
}

// ================= mma.sync causal flash attention ===========================
// bf16 3-pass (unchanged math). qb reversed so longest CTAs start first.
// Epilogue writes fp16 single (O-proj A operand).
#define FROWE 136
#define FROWB (FROWE * 2)
#define FQ_PART (128 * FROWB)
#define FKV_PART (64 * FROWB)
#define FSTAGE (4 * FKV_PART)
#define FQLO_OFF FQ_PART
#define FSTAGE_OFF (2 * FQ_PART)
#define FLASH_SMEM (FSTAGE_OFF + 2 * FSTAGE)   // 208896

__global__ void __launch_bounds__(256, 1) flash_mma_kernel(__half* __restrict__ outh)
{
    extern __shared__ char fsm[];
    const uint32_t sb = smem_u32(fsm);
    const int qb = (gridDim.x - 1) - blockIdx.x;   // longest work first
    const int h = blockIdx.y, b = blockIdx.z;
    const int tid = threadIdx.x, lane = tid & 31, w = tid >> 5;

    const size_t headoff = ((size_t)(b * NHEADS + h) * TSEQ) * HDIM;
    const __nv_bfloat16* qh = g_qhi + headoff + (size_t)qb * 128 * HDIM;
    const __nv_bfloat16* ql = g_qlo + headoff + (size_t)qb * 128 * HDIM;
    const __nv_bfloat16* kh = g_khi + headoff;
    const __nv_bfloat16* kl = g_klo + headoff;
    const __nv_bfloat16* vh = g_vhi + headoff;
    const __nv_bfloat16* vl = g_vlo + headoff;

    #pragma unroll
    for (int t = 0; t < 16; t++) {
        int cid = tid + t * 256;
        int part = cid >> 11;
        int pc = cid & 2047;
        int r = pc >> 4, cq = pc & 15;
        uint32_t dst = sb + part * FQ_PART + r * FROWB + cq * 16;
        const __nv_bfloat16* s = part ? ql : qh;
        cp16(dst, s + (size_t)r * HDIM + cq * 8);
    }

    auto load_kv = [&](int j, int stage) {
        uint32_t base = sb + FSTAGE_OFF + stage * FSTAGE;
        const __nv_bfloat16* srcs[4] = {
            kh + (size_t)j * 64 * HDIM, kl + (size_t)j * 64 * HDIM,
            vh + (size_t)j * 64 * HDIM, vl + (size_t)j * 64 * HDIM };
        #pragma unroll
        for (int t = 0; t < 16; t++) {
            int cid = tid + t * 256;
            int part = cid >> 10;
            int pc = cid & 1023;
            int r = pc >> 4, cq = pc & 15;
            cp16(base + part * FKV_PART + r * FROWB + cq * 16,
                 srcs[part] + (size_t)r * HDIM + cq * 8);
        }
    };

    const int nj = 2 * qb + 2;
    load_kv(0, 0); CP_COMMIT();
    load_kv(1, 1); CP_COMMIT();

    float oacc[16][4];
    #pragma unroll
    for (int i = 0; i < 16; i++)
        #pragma unroll
        for (int e = 0; e < 4; e++) oacc[i][e] = 0.f;
    float m_s[2] = {-1e30f, -1e30f};
    float l_s[2] = {0.f, 0.f};
    const float scale = 0.08838834764831845f;

    for (int j = 0; j < nj; j++) {
        CP_WAIT(1);
        __syncthreads();
        uint32_t stg = sb + FSTAGE_OFF + (j & 1) * FSTAGE;

        float sacc[8][4];
        #pragma unroll
        for (int i = 0; i < 8; i++)
            #pragma unroll
            for (int e = 0; e < 4; e++) sacc[i][e] = 0.f;

        const int qd = lane >> 3;
        #pragma unroll
        for (int kc = 0; kc < 8; kc++) {
            uint32_t ahr[4], alr[4];
            uint32_t arow = w * 16 + (lane & 15);
            uint32_t aad = sb + arow * FROWB + kc * 32 + (lane >> 4) * 16;
            LDMX4(ahr, aad);
            LDMX4(alr, aad + FQLO_OFF);
            #pragma unroll
            for (int nt2 = 0; nt2 < 4; nt2++) {
                uint32_t brow = nt2 * 16 + (qd >> 1) * 8 + (lane & 7);
                uint32_t bad = stg + brow * FROWB + kc * 32 + (qd & 1) * 16;
                uint32_t bh4[4], bl4[4];
                LDMX4(bh4, bad);
                LDMX4(bl4, bad + FKV_PART);
                uint32_t b0h[2] = {bh4[0], bh4[1]}, b1h[2] = {bh4[2], bh4[3]};
                uint32_t b0l[2] = {bl4[0], bl4[1]}, b1l[2] = {bl4[2], bl4[3]};
                MMA16816(sacc[nt2*2],   ahr, b0h);
                MMA16816(sacc[nt2*2+1], ahr, b1h);
                MMA16816(sacc[nt2*2],   ahr, b0l);
                MMA16816(sacc[nt2*2+1], ahr, b1l);
                MMA16816(sacc[nt2*2],   alr, b0h);
                MMA16816(sacc[nt2*2+1], alr, b1h);
            }
        }

        const bool need_mask = (j >= 2 * qb);
        const int rowg0 = qb * 128 + w * 16 + (lane >> 2);
        const int colb = j * 64 + (lane & 3) * 2;
        #pragma unroll
        for (int half = 0; half < 2; half++) {
            int rowg = rowg0 + half * 8;
            float mloc = -1e30f;
            #pragma unroll
            for (int nt = 0; nt < 8; nt++) {
                float v0 = sacc[nt][half*2]     * scale;
                float v1 = sacc[nt][half*2 + 1] * scale;
                if (need_mask) {
                    if (colb + nt * 8     > rowg) v0 = -1e30f;
                    if (colb + nt * 8 + 1 > rowg) v1 = -1e30f;
                }
                sacc[nt][half*2]     = v0;
                sacc[nt][half*2 + 1] = v1;
                mloc = fmaxf(mloc, fmaxf(v0, v1));
            }
            mloc = fmaxf(mloc, __shfl_xor_sync(0xffffffffu, mloc, 1));
            mloc = fmaxf(mloc, __shfl_xor_sync(0xffffffffu, mloc, 2));
            float mn = fmaxf(m_s[half], mloc);
            float corr = __expf(m_s[half] - mn);
            m_s[half] = mn;
            float rsum = 0.f;
            #pragma unroll
            for (int nt = 0; nt < 8; nt++) {
                float p0 = __expf(sacc[nt][half*2]     - mn);
                float p1 = __expf(sacc[nt][half*2 + 1] - mn);
                sacc[nt][half*2]     = p0;
                sacc[nt][half*2 + 1] = p1;
                rsum += p0 + p1;
            }
            rsum += __shfl_xor_sync(0xffffffffu, rsum, 1);
            rsum += __shfl_xor_sync(0xffffffffu, rsum, 2);
            l_s[half] = l_s[half] * corr + rsum;
            #pragma unroll
            for (int nt = 0; nt < 16; nt++) {
                oacc[nt][half*2]     *= corr;
                oacc[nt][half*2 + 1] *= corr;
            }
        }

        #pragma unroll
        for (int kc2 = 0; kc2 < 4; kc2++) {
            uint32_t phi[4], plo[4];
            #pragma unroll
            for (int e = 0; e < 4; e++) {
                int nt = 2 * kc2 + (e >> 1);
                int co = (e & 1) * 2;
                float p0 = sacc[nt][co], p1 = sacc[nt][co + 1];
                uint32_t ph;
                asm("cvt.rn.bf16x2.f32 %0, %1, %2;" : "=r"(ph) : "f"(p1), "f"(p0));
                float h0 = __uint_as_float(ph << 16);
                float h1 = __uint_as_float(ph & 0xffff0000u);
                uint32_t pl;
                asm("cvt.rn.bf16x2.f32 %0, %1, %2;" : "=r"(pl) : "f"(p1 - h1), "f"(p0 - h0));
                phi[e] = ph; plo[e] = pl;
            }
            #pragma unroll
            for (int nt8 = 0; nt8 < 8; nt8++) {
                uint32_t vrow = kc2 * 16 + (qd & 1) * 8 + (lane & 7);
                uint32_t vad = stg + 2 * FKV_PART + vrow * FROWB + nt8 * 32 + (qd >> 1) * 16;
                uint32_t vh4[4], vl4[4];
                LDMX4T(vh4, vad);
                LDMX4T(vl4, vad + FKV_PART);
                uint32_t v0h[2] = {vh4[0], vh4[1]}, v1h[2] = {vh4[2], vh4[3]};
                uint32_t v0l[2] = {vl4[0], vl4[1]}, v1l[2] = {vl4[2], vl4[3]};
                MMA16816(oacc[nt8*2],   phi, v0h);
                MMA16816(oacc[nt8*2+1], phi, v1h);
                MMA16816(oacc[nt8*2],   phi, v0l);
                MMA16816(oacc[nt8*2+1], phi, v1l);
                MMA16816(oacc[nt8*2],   plo, v0h);
                MMA16816(oacc[nt8*2+1], plo, v1h);
            }
        }

        __syncthreads();
        if (j + 2 < nj) load_kv(j + 2, j & 1);
        CP_COMMIT();
    }

    // ---- epilogue: normalize, write fp16 single [B,T,H] ----
    #pragma unroll
    for (int half = 0; half < 2; half++) {
        float inv = 1.0f / l_s[half];
        int t = qb * 128 + w * 16 + (lane >> 2) + half * 8;
        size_t rowoff = (((size_t)(b * TSEQ + t) * NHEADS + h) * HDIM);
        #pragma unroll
        for (int nt = 0; nt < 16; nt++) {
            int d = nt * 8 + (lane & 3) * 2;
            float y0 = oacc[nt][half*2] * inv;
            float y1 = oacc[nt][half*2 + 1] * inv;
            *(__half2*)(outh + rowoff + d) = __floats2half2_rn(y0, y1);
        }
    }
}

// ---------------- launch -----------------------------------------------------
extern "C" void kernel_launch(void* const* d_in, const int* in_sizes, int n_in,
                              void* d_out, int out_size) {
    const float* x  = (const float*)d_in[0];
    const float* Wq = (const float*)d_in[1];
    const float* Wk = (const float*)d_in[2];
    const float* Wv = (const float*)d_in[3];
    const float* Wo = (const float*)d_in[4];
    float* out = (float*)d_out;

    __half *xh, *wh, *wl, *aoh;
    cudaGetSymbolAddress((void**)&xh,  g_xh);
    cudaGetSymbolAddress((void**)&wh,  g_wh);
    cudaGetSymbolAddress((void**)&wl,  g_wl);
    cudaGetSymbolAddress((void**)&aoh, g_aoh);

    cudaFuncSetAttribute(tc_gemm_kernel<0>,
                         cudaFuncAttributeMaxDynamicSharedMemorySize, GEMM_SMEM);
    cudaFuncSetAttribute(tc_gemm_kernel<1>,
                         cudaFuncAttributeMaxDynamicSharedMemorySize, GEMM_SMEM);
    cudaFuncSetAttribute(flash_mma_kernel,
                         cudaFuncAttributeMaxDynamicSharedMemorySize, FLASH_SMEM);

    rope_table_kernel<<<(TSEQ * 64 + 255) / 256, 256>>>();

    const int NX4 = MROWS * HMODEL / 4;
    const int NW4 = HMODEL * HMODEL / 4;
    const size_t WSTRIDE = (size_t)HMODEL * HMODEL;
    tofp16_kernel<<<(NX4 + 255) / 256, 256>>>(x, xh, NX4);
    split_w_kernel<<<dim3(NW4 / 256, 4), 256>>>(Wq, Wk, Wv, Wo);

    // ONE fused QKV GEMM (B = [6144,2048], wq|wk|wv hi/lo contiguous)
    dim3 qkvgrid(3 * HMODEL / 128, MROWS / 128);   // (48, 64)
    tc_gemm_kernel<1><<<qkvgrid, 256, GEMM_SMEM>>>(xh, wh, wl, nullptr);

    flash_mma_kernel<<<dim3(TSEQ / 128, NHEADS, BATCH), 256, FLASH_SMEM>>>(aoh);

    dim3 ogrid(HMODEL / 128, MROWS / 128);   // (16, 64)
    tc_gemm_kernel<0><<<ogrid, 256, GEMM_SMEM>>>(aoh, wh + 3 * WSTRIDE, wl + 3 * WSTRIDE, out);
}

// round 13
// speedup vs baseline: 1.6496x; 1.6496x over previous
#include <cuda_runtime.h>
#include <cuda_bf16.h>
#include <cuda_fp16.h>
#include <math.h>
#include <stdint.h>

#define NHEADS 16
#define HDIM 128
#define TSEQ 2048
#define BATCH 4
#define HMODEL 2048
#define MROWS (BATCH*TSEQ)   // 8192

// ---------------- scratch (device globals: allocation-free) ----------------
__device__ float g_cos[TSEQ*64];
__device__ float g_sin[TSEQ*64];
// fp16 operands for projection GEMMs (A single, B hi/lo)
__device__ __half g_xh[(size_t)MROWS*HMODEL];
__device__ __half g_wh[4][(size_t)HMODEL*HMODEL];   // q,k,v,o contiguous
__device__ __half g_wl[4][(size_t)HMODEL*HMODEL];
__device__ __half g_aoh[(size_t)MROWS*HMODEL];
// fp16 q single + k/v hi/lo for flash (post-RoPE), written by QKV GEMM epilogue
__device__ __half g_qh[(size_t)BATCH*NHEADS*TSEQ*HDIM];
__device__ __half g_kh[(size_t)BATCH*NHEADS*TSEQ*HDIM];
__device__ __half g_kl[(size_t)BATCH*NHEADS*TSEQ*HDIM];
__device__ __half g_vh[(size_t)BATCH*NHEADS*TSEQ*HDIM];
__device__ __half g_vl[(size_t)BATCH*NHEADS*TSEQ*HDIM];

// ================= PTX helpers (baseline ISA only) ==========================
__device__ __forceinline__ uint32_t smem_u32(const void* p) {
    uint32_t a;
    asm("{ .reg .u64 t; cvta.to.shared.u64 t, %1; cvt.u32.u64 %0, t; }" : "=r"(a) : "l"(p));
    return a;
}
__device__ __forceinline__ void cp16(uint32_t dst, const void* src) {
    asm volatile("cp.async.cg.shared.global [%0], [%1], 16;" :: "r"(dst), "l"(src));
}
#define CP_COMMIT() asm volatile("cp.async.commit_group;" ::: "memory")
#define CP_WAIT(n)  asm volatile("cp.async.wait_group %0;" :: "n"(n) : "memory")

#define LDMX4(r, addr) \
    asm volatile("ldmatrix.sync.aligned.m8n8.x4.shared.b16 {%0,%1,%2,%3}, [%4];" \
        : "=r"((r)[0]), "=r"((r)[1]), "=r"((r)[2]), "=r"((r)[3]) : "r"(addr))
#define LDMX4T(r, addr) \
    asm volatile("ldmatrix.sync.aligned.m8n8.x4.trans.shared.b16 {%0,%1,%2,%3}, [%4];" \
        : "=r"((r)[0]), "=r"((r)[1]), "=r"((r)[2]), "=r"((r)[3]) : "r"(addr))

#define MMAF16(c, a, b) \
    asm volatile("mma.sync.aligned.m16n8k16.row.col.f32.f16.f16.f32 " \
        "{%0,%1,%2,%3}, {%4,%5,%6,%7}, {%8,%9}, {%0,%1,%2,%3};" \
        : "+f"((c)[0]), "+f"((c)[1]), "+f"((c)[2]), "+f"((c)[3]) \
        : "r"((a)[0]), "r"((a)[1]), "r"((a)[2]), "r"((a)[3]), "r"((b)[0]), "r"((b)[1]))

// ---------------- fp32 -> fp16 single convert (x) -----------------------------
__global__ void tofp16_kernel(const float* __restrict__ src,
                              __half* __restrict__ dst, int n4) {
    int i = blockIdx.x * blockDim.x + threadIdx.x;
    if (i >= n4) return;
    float4 v = ((const float4*)src)[i];
    ((__half2*)dst)[2*i]   = __floats2half2_rn(v.x, v.y);
    ((__half2*)dst)[2*i+1] = __floats2half2_rn(v.z, v.w);
}

// ---- fused 4-matrix W split to fp16 hi/lo (one launch) ----
__global__ void split_w_kernel(const float* __restrict__ w0, const float* __restrict__ w1,
                               const float* __restrict__ w2, const float* __restrict__ w3) {
    const float* srcs[4] = {w0, w1, w2, w3};
    int m = blockIdx.y;
    const float* src = srcs[m];
    __half* hi = g_wh[m];
    __half* lo = g_wl[m];
    int i = blockIdx.x * blockDim.x + threadIdx.x;
    float4 v = ((const float4*)src)[i];
    float vs[4] = {v.x, v.y, v.z, v.w};
    __half h[4], l[4];
    #pragma unroll
    for (int j = 0; j < 4; j++) {
        h[j] = __float2half(vs[j]);
        l[j] = __float2half(vs[j] - __half2float(h[j]));
    }
    __half2 h0; h0.x = h[0]; h0.y = h[1];
    __half2 h1; h1.x = h[2]; h1.y = h[3];
    __half2 l0; l0.x = l[0]; l0.y = l[1];
    __half2 l1; l1.x = l[2]; l1.y = l[3];
    ((__half2*)hi)[2*i]   = h0;
    ((__half2*)hi)[2*i+1] = h1;
    ((__half2*)lo)[2*i]   = l0;
    ((__half2*)lo)[2*i+1] = l1;
}

// ---------------- RoPE table -------------------------------------------------
__global__ void rope_table_kernel() {
    int i = blockIdx.x * blockDim.x + threadIdx.x;
    if (i >= TSEQ * 64) return;
    int t = i >> 6, d = i & 63;
    double inv = exp(-((double)(2 * d) / 128.0) * log(10000.0));
    double ang = (double)t * inv;
    double s, c;
    sincos(ang, &s, &c);
    g_cos[i] = (float)c;
    g_sin[i] = (float)s;
}

// ================= warp-mma fp16 2-pass GEMM (occ=2, 2-stage BK32) ===========
// C = A*Bh + A*Bl (A single fp16, B hi/lo).
// MODE 0: C fp32 [M,2048]. MODE 1: fused QKV with RoPE epilogue writing
//         q single / k,v hi/lo fp16 into flash layout.
#define ROWB 80
#define PART (128 * ROWB)          // 10240
#define STG  (3 * PART)            // 30720 per stage
#define NSTG 2
#define TILEPAD 130
#define GEMM_SMEM 66560            // max(2*STG, 128*130*4)

template<int MODE>
__global__ void __launch_bounds__(256, 2)
tc_gemm_kernel(const __half* __restrict__ A,
               const __half* __restrict__ Bhi, const __half* __restrict__ Blo,
               float* __restrict__ C0)
{
    extern __shared__ char smem[];
    const uint32_t sb = smem_u32(smem);
    const int tid = threadIdx.x;
    const int lane = tid & 31, w = tid >> 5;
    const int wm = w & 1, wn = w >> 1;

    const __half* aP = A   + (size_t)blockIdx.y * 128 * HMODEL;
    const __half* bH = Bhi + (size_t)blockIdx.x * 128 * HMODEL;
    const __half* bL = Blo + (size_t)blockIdx.x * 128 * HMODEL;

    const int c0 = tid, c1 = tid + 256;
    const int r0 = c0 >> 2, q0 = c0 & 3;
    const int r1 = c1 >> 2, q1 = c1 & 3;

    auto load_stage = [&](int s, int kc) {
        uint32_t base = sb + s * STG;
        size_t g0 = (size_t)r0 * HMODEL + kc * 32 + q0 * 8;
        size_t g1 = (size_t)r1 * HMODEL + kc * 32 + q1 * 8;
        uint32_t d0 = base + r0 * ROWB + q0 * 16;
        uint32_t d1 = base + r1 * ROWB + q1 * 16;
        cp16(d0,            aP + g0);  cp16(d1,            aP + g1);
        cp16(d0 + PART,     bH + g0);  cp16(d1 + PART,     bH + g1);
        cp16(d0 + 2*PART,   bL + g0);  cp16(d1 + 2*PART,   bL + g1);
    };

    float acc[4][4][4];
    #pragma unroll
    for (int i = 0; i < 4; i++)
        #pragma unroll
        for (int j = 0; j < 4; j++)
            #pragma unroll
            for (int e = 0; e < 4; e++) acc[i][j][e] = 0.f;

    load_stage(0, 0); CP_COMMIT();
    load_stage(1, 1); CP_COMMIT();

    const int NKC = HMODEL / 32;   // 64
    for (int kc = 0; kc < NKC; kc++) {
        CP_WAIT(1);
        __syncthreads();
        uint32_t stage = sb + (kc & 1) * STG;

        #pragma unroll
        for (int step = 0; step < 2; step++) {
            uint32_t bhi[4][2], blo[4][2];
            const int qd = lane >> 3;
            #pragma unroll
            for (int nt2 = 0; nt2 < 2; nt2++) {
                uint32_t brow = wn * 32 + nt2 * 16 + (qd >> 1) * 8 + (lane & 7);
                uint32_t bd = stage + PART + brow * ROWB + step * 32 + (qd & 1) * 16;
                uint32_t th[4], tl[4];
                LDMX4(th, bd);
                LDMX4(tl, bd + PART);
                bhi[nt2*2][0] = th[0]; bhi[nt2*2][1] = th[1];
                bhi[nt2*2+1][0] = th[2]; bhi[nt2*2+1][1] = th[3];
                blo[nt2*2][0] = tl[0]; blo[nt2*2][1] = tl[1];
                blo[nt2*2+1][0] = tl[2]; blo[nt2*2+1][1] = tl[3];
            }
            #pragma unroll
            for (int mt = 0; mt < 4; mt++) {
                uint32_t ah[4];
                uint32_t arow = wm * 64 + mt * 16 + (lane & 15);
                uint32_t ad = stage + arow * ROWB + step * 32 + (lane >> 4) * 16;
                LDMX4(ah, ad);
                #pragma unroll
                for (int nt = 0; nt < 4; nt++) MMAF16(acc[mt][nt], ah, bhi[nt]);
                #pragma unroll
                for (int nt = 0; nt < 4; nt++) MMAF16(acc[mt][nt], ah, blo[nt]);
            }
        }
        __syncthreads();
        if (kc + 2 < NKC) load_stage(kc & 1, kc + 2);
        CP_COMMIT();
    }

    if (MODE == 0) {
        #pragma unroll
        for (int mt = 0; mt < 4; mt++) {
            int mrow = blockIdx.y * 128 + wm * 64 + mt * 16 + (lane >> 2);
            #pragma unroll
            for (int nt = 0; nt < 4; nt++) {
                int n = blockIdx.x * 128 + wn * 32 + nt * 8 + (lane & 3) * 2;
                float* dst = C0 + (size_t)mrow * HMODEL + n;
                *(float2*)dst = make_float2(acc[mt][nt][0], acc[mt][nt][1]);
                *(float2*)(dst + 8 * HMODEL) = make_float2(acc[mt][nt][2], acc[mt][nt][3]);
            }
        }
    } else {
        float* tile = (float*)smem;   // [128][TILEPAD]
        #pragma unroll
        for (int mt = 0; mt < 4; mt++) {
            int rl = wm * 64 + mt * 16 + (lane >> 2);
            #pragma unroll
            for (int nt = 0; nt < 4; nt++) {
                int cl = wn * 32 + nt * 8 + (lane & 3) * 2;
                tile[rl * TILEPAD + cl]       = acc[mt][nt][0];
                tile[rl * TILEPAD + cl + 1]   = acc[mt][nt][1];
                tile[(rl + 8) * TILEPAD + cl]     = acc[mt][nt][2];
                tile[(rl + 8) * TILEPAD + cl + 1] = acc[mt][nt][3];
            }
        }
        __syncthreads();

        const int matrix = blockIdx.x >> 4;     // 0:q 1:k 2:v
        const int head   = blockIdx.x & 15;
        __half* hi = (matrix == 0) ? g_qh : (matrix == 1) ? g_kh : g_vh;
        __half* lo = (matrix == 1) ? g_kl : g_vl;    // unused for q
        const bool dorope = (matrix < 2);
        const bool dolo = (matrix != 0);

        #pragma unroll
        for (int it = 0; it < 16; it++) {
            int idx = tid + it * 256;
            int rl = idx >> 5;
            int dp = (idx & 31) * 2;
            int mrow = blockIdx.y * 128 + rl;
            int b = mrow >> 11, t = mrow & (TSEQ - 1);
            float x0a = tile[rl * TILEPAD + dp];
            float x0b = tile[rl * TILEPAD + dp + 1];
            float x1a = tile[rl * TILEPAD + dp + 64];
            float x1b = tile[rl * TILEPAD + dp + 65];
            float y0a, y0b, y1a, y1b;
            if (dorope) {
                float c0 = g_cos[t * 64 + dp],     s0 = g_sin[t * 64 + dp];
                float c1 = g_cos[t * 64 + dp + 1], s1 = g_sin[t * 64 + dp + 1];
                y0a = x0a * c0 - x1a * s0;  y1a = x1a * c0 + x0a * s0;
                y0b = x0b * c1 - x1b * s1;  y1b = x1b * c1 + x0b * s1;
            } else {
                y0a = x0a; y0b = x0b; y1a = x1a; y1b = x1b;
            }
            size_t base = ((size_t)(b * NHEADS + head) * TSEQ + t) * HDIM;
            __half2 hv0 = __floats2half2_rn(y0a, y0b);
            __half2 hv1 = __floats2half2_rn(y1a, y1b);
            *(__half2*)(hi + base + dp)      = hv0;
            *(__half2*)(hi + base + dp + 64) = hv1;
            if (dolo) {
                __half2 lv0 = __floats2half2_rn(y0a - __half2float(hv0.x),
                                                y0b - __half2float(hv0.y));
                __half2 lv1 = __floats2half2_rn(y1a - __half2float(hv1.x),
                                                y1b - __half2float(hv1.y));
                *(__half2*)(lo + base + dp)      = lv0;
                *(__half2*)(lo + base + dp + 64) = lv1;
            }
        }
    }
}

// ================= mma.sync causal flash attention (fp16 2-pass) =============
// Q single fp16, K/V hi/lo fp16. S = Q*Kh + Q*Kl; O += P*Vh + P*Vl (P single).
#define FROWE 136
#define FROWB (FROWE * 2)
#define FQ_PART (128 * FROWB)        // 34816 (single Q part)
#define FKV_PART (64 * FROWB)        // 17408
#define FSTAGE (4 * FKV_PART)        // 69632 (kh,kl,vh,vl)
#define FSTAGE_OFF FQ_PART
#define FLASH_SMEM (FSTAGE_OFF + 2 * FSTAGE)   // 174080

__global__ void __launch_bounds__(256, 1) flash_mma_kernel(__half* __restrict__ outh)
{
    extern __shared__ char fsm[];
    const uint32_t sb = smem_u32(fsm);
    const int qb = (gridDim.x - 1) - blockIdx.x;   // longest work first
    const int h = blockIdx.y, b = blockIdx.z;
    const int tid = threadIdx.x, lane = tid & 31, w = tid >> 5;

    const size_t headoff = ((size_t)(b * NHEADS + h) * TSEQ) * HDIM;
    const __half* qp = g_qh + headoff + (size_t)qb * 128 * HDIM;
    const __half* kh = g_kh + headoff;
    const __half* kl = g_kl + headoff;
    const __half* vh = g_vh + headoff;
    const __half* vl = g_vl + headoff;

    // ---- load Q (single): 2048 x 16B chunks ----
    #pragma unroll
    for (int t = 0; t < 8; t++) {
        int cid = tid + t * 256;
        int r = cid >> 4, cq = cid & 15;
        cp16(sb + r * FROWB + cq * 16, qp + (size_t)r * HDIM + cq * 8);
    }

    auto load_kv = [&](int j, int stage) {
        uint32_t base = sb + FSTAGE_OFF + stage * FSTAGE;
        const __half* srcs[4] = {
            kh + (size_t)j * 64 * HDIM, kl + (size_t)j * 64 * HDIM,
            vh + (size_t)j * 64 * HDIM, vl + (size_t)j * 64 * HDIM };
        #pragma unroll
        for (int t = 0; t < 16; t++) {
            int cid = tid + t * 256;
            int part = cid >> 10;
            int pc = cid & 1023;
            int r = pc >> 4, cq = pc & 15;
            cp16(base + part * FKV_PART + r * FROWB + cq * 16,
                 srcs[part] + (size_t)r * HDIM + cq * 8);
        }
    };

    const int nj = 2 * qb + 2;
    load_kv(0, 0); CP_COMMIT();
    load_kv(1, 1); CP_COMMIT();

    float oacc[16][4];
    #pragma unroll
    for (int i = 0; i < 16; i++)
        #pragma unroll
        for (int e = 0; e < 4; e++) oacc[i][e] = 0.f;
    float m_s[2] = {-1e30f, -1e30f};
    float l_s[2] = {0.f, 0.f};
    const float scale = 0.08838834764831845f;

    for (int j = 0; j < nj; j++) {
        CP_WAIT(1);
        __syncthreads();
        uint32_t stg = sb + FSTAGE_OFF + (j & 1) * FSTAGE;

        float sacc[8][4];
        #pragma unroll
        for (int i = 0; i < 8; i++)
            #pragma unroll
            for (int e = 0; e < 4; e++) sacc[i][e] = 0.f;

        const int qd = lane >> 3;
        #pragma unroll
        for (int kc = 0; kc < 8; kc++) {
            uint32_t ah[4];
            uint32_t arow = w * 16 + (lane & 15);
            uint32_t aad = sb + arow * FROWB + kc * 32 + (lane >> 4) * 16;
            LDMX4(ah, aad);
            #pragma unroll
            for (int nt2 = 0; nt2 < 4; nt2++) {
                uint32_t brow = nt2 * 16 + (qd >> 1) * 8 + (lane & 7);
                uint32_t bad = stg + brow * FROWB + kc * 32 + (qd & 1) * 16;
                uint32_t bh4[4], bl4[4];
                LDMX4(bh4, bad);
                LDMX4(bl4, bad + FKV_PART);
                uint32_t b0h[2] = {bh4[0], bh4[1]}, b1h[2] = {bh4[2], bh4[3]};
                uint32_t b0l[2] = {bl4[0], bl4[1]}, b1l[2] = {bl4[2], bl4[3]};
                MMAF16(sacc[nt2*2],   ah, b0h);
                MMAF16(sacc[nt2*2+1], ah, b1h);
                MMAF16(sacc[nt2*2],   ah, b0l);
                MMAF16(sacc[nt2*2+1], ah, b1l);
            }
        }

        const bool need_mask = (j >= 2 * qb);
        const int rowg0 = qb * 128 + w * 16 + (lane >> 2);
        const int colb = j * 64 + (lane & 3) * 2;
        #pragma unroll
        for (int half = 0; half < 2; half++) {
            int rowg = rowg0 + half * 8;
            float mloc = -1e30f;
            #pragma unroll
            for (int nt = 0; nt < 8; nt++) {
                float v0 = sacc[nt][half*2]     * scale;
                float v1 = sacc[nt][half*2 + 1] * scale;
                if (need_mask) {
                    if (colb + nt * 8     > rowg) v0 = -1e30f;
                    if (colb + nt * 8 + 1 > rowg) v1 = -1e30f;
                }
                sacc[nt][half*2]     = v0;
                sacc[nt][half*2 + 1] = v1;
                mloc = fmaxf(mloc, fmaxf(v0, v1));
            }
            mloc = fmaxf(mloc, __shfl_xor_sync(0xffffffffu, mloc, 1));
            mloc = fmaxf(mloc, __shfl_xor_sync(0xffffffffu, mloc, 2));
            float mn = fmaxf(m_s[half], mloc);
            float corr = __expf(m_s[half] - mn);
            m_s[half] = mn;
            float rsum = 0.f;
            #pragma unroll
            for (int nt = 0; nt < 8; nt++) {
                float p0 = __expf(sacc[nt][half*2]     - mn);
                float p1 = __expf(sacc[nt][half*2 + 1] - mn);
                sacc[nt][half*2]     = p0;
                sacc[nt][half*2 + 1] = p1;
                rsum += p0 + p1;
            }
            rsum += __shfl_xor_sync(0xffffffffu, rsum, 1);
            rsum += __shfl_xor_sync(0xffffffffu, rsum, 2);
            l_s[half] = l_s[half] * corr + rsum;
            #pragma unroll
            for (int nt = 0; nt < 16; nt++) {
                oacc[nt][half*2]     *= corr;
                oacc[nt][half*2 + 1] *= corr;
            }
        }

        #pragma unroll
        for (int kc2 = 0; kc2 < 4; kc2++) {
            uint32_t pf[4];
            #pragma unroll
            for (int e = 0; e < 4; e++) {
                int nt = 2 * kc2 + (e >> 1);
                int co = (e & 1) * 2;
                asm("cvt.rn.f16x2.f32 %0, %1, %2;"
                    : "=r"(pf[e]) : "f"(sacc[nt][co + 1]), "f"(sacc[nt][co]));
            }
            #pragma unroll
            for (int nt8 = 0; nt8 < 8; nt8++) {
                uint32_t vrow = kc2 * 16 + (qd & 1) * 8 + (lane & 7);
                uint32_t vad = stg + 2 * FKV_PART + vrow * FROWB + nt8 * 32 + (qd >> 1) * 16;
                uint32_t vh4[4], vl4[4];
                LDMX4T(vh4, vad);
                LDMX4T(vl4, vad + FKV_PART);
                uint32_t v0h[2] = {vh4[0], vh4[1]}, v1h[2] = {vh4[2], vh4[3]};
                uint32_t v0l[2] = {vl4[0], vl4[1]}, v1l[2] = {vl4[2], vl4[3]};
                MMAF16(oacc[nt8*2],   pf, v0h);
                MMAF16(oacc[nt8*2+1], pf, v1h);
                MMAF16(oacc[nt8*2],   pf, v0l);
                MMAF16(oacc[nt8*2+1], pf, v1l);
            }
        }

        __syncthreads();
        if (j + 2 < nj) load_kv(j + 2, j & 1);
        CP_COMMIT();
    }

    // ---- epilogue: normalize, write fp16 single [B,T,H] ----
    #pragma unroll
    for (int half = 0; half < 2; half++) {
        float inv = 1.0f / l_s[half];
        int t = qb * 128 + w * 16 + (lane >> 2) + half * 8;
        size_t rowoff = (((size_t)(b * TSEQ + t) * NHEADS + h) * HDIM);
        #pragma unroll
        for (int nt = 0; nt < 16; nt++) {
            int d = nt * 8 + (lane & 3) * 2;
            float y0 = oacc[nt][half*2] * inv;
            float y1 = oacc[nt][half*2 + 1] * inv;
            *(__half2*)(outh + rowoff + d) = __floats2half2_rn(y0, y1);
        }
    }
}

// ---------------- launch -----------------------------------------------------
extern "C" void kernel_launch(void* const* d_in, const int* in_sizes, int n_in,
                              void* d_out, int out_size) {
    const float* x  = (const float*)d_in[0];
    const float* Wq = (const float*)d_in[1];
    const float* Wk = (const float*)d_in[2];
    const float* Wv = (const float*)d_in[3];
    const float* Wo = (const float*)d_in[4];
    float* out = (float*)d_out;

    __half *xh, *wh, *wl, *aoh;
    cudaGetSymbolAddress((void**)&xh,  g_xh);
    cudaGetSymbolAddress((void**)&wh,  g_wh);
    cudaGetSymbolAddress((void**)&wl,  g_wl);
    cudaGetSymbolAddress((void**)&aoh, g_aoh);

    cudaFuncSetAttribute(tc_gemm_kernel<0>,
                         cudaFuncAttributeMaxDynamicSharedMemorySize, GEMM_SMEM);
    cudaFuncSetAttribute(tc_gemm_kernel<1>,
                         cudaFuncAttributeMaxDynamicSharedMemorySize, GEMM_SMEM);
    cudaFuncSetAttribute(flash_mma_kernel,
                         cudaFuncAttributeMaxDynamicSharedMemorySize, FLASH_SMEM);

    rope_table_kernel<<<(TSEQ * 64 + 255) / 256, 256>>>();

    const int NX4 = MROWS * HMODEL / 4;
    const int NW4 = HMODEL * HMODEL / 4;
    const size_t WSTRIDE = (size_t)HMODEL * HMODEL;
    tofp16_kernel<<<(NX4 + 255) / 256, 256>>>(x, xh, NX4);
    split_w_kernel<<<dim3(NW4 / 256, 4), 256>>>(Wq, Wk, Wv, Wo);

    dim3 qkvgrid(3 * HMODEL / 128, MROWS / 128);   // (48, 64)
    tc_gemm_kernel<1><<<qkvgrid, 256, GEMM_SMEM>>>(xh, wh, wl, nullptr);

    flash_mma_kernel<<<dim3(TSEQ / 128, NHEADS, BATCH), 256, FLASH_SMEM>>>(aoh);

    dim3 ogrid(HMODEL / 128, MROWS / 128);   // (16, 64)
    tc_gemm_kernel<0><<<ogrid, 256, GEMM_SMEM>>>(aoh, wh + 3 * WSTRIDE, wl + 3 * WSTRIDE, out);
}

// round 14
// speedup vs baseline: 1.8337x; 1.1116x over previous
#include <cuda_runtime.h>
#include <cuda_bf16.h>
#include <cuda_fp16.h>
#include <math.h>
#include <stdint.h>

#define NHEADS 16
#define HDIM 128
#define TSEQ 2048
#define BATCH 4
#define HMODEL 2048
#define MROWS (BATCH*TSEQ)   // 8192

// ---------------- scratch (device globals: allocation-free) ----------------
__device__ float g_cos[TSEQ*64];
__device__ float g_sin[TSEQ*64];
// fp16 operands for projection GEMMs (A single, B hi/lo)
__device__ __half g_xh[(size_t)MROWS*HMODEL];
__device__ __half g_wh[4][(size_t)HMODEL*HMODEL];   // q,k,v,o contiguous
__device__ __half g_wl[4][(size_t)HMODEL*HMODEL];
__device__ __half g_aoh[(size_t)MROWS*HMODEL];
// fp16 q/k/v single for flash (post-RoPE), written by QKV GEMM epilogue
__device__ __half g_qh[(size_t)BATCH*NHEADS*TSEQ*HDIM];
__device__ __half g_kh[(size_t)BATCH*NHEADS*TSEQ*HDIM];
__device__ __half g_vh[(size_t)BATCH*NHEADS*TSEQ*HDIM];

// ================= PTX helpers (baseline ISA only) ==========================
__device__ __forceinline__ uint32_t smem_u32(const void* p) {
    uint32_t a;
    asm("{ .reg .u64 t; cvta.to.shared.u64 t, %1; cvt.u32.u64 %0, t; }" : "=r"(a) : "l"(p));
    return a;
}
__device__ __forceinline__ void cp16(uint32_t dst, const void* src) {
    asm volatile("cp.async.cg.shared.global [%0], [%1], 16;" :: "r"(dst), "l"(src));
}
#define CP_COMMIT() asm volatile("cp.async.commit_group;" ::: "memory")
#define CP_WAIT(n)  asm volatile("cp.async.wait_group %0;" :: "n"(n) : "memory")

#define LDMX4(r, addr) \
    asm volatile("ldmatrix.sync.aligned.m8n8.x4.shared.b16 {%0,%1,%2,%3}, [%4];" \
        : "=r"((r)[0]), "=r"((r)[1]), "=r"((r)[2]), "=r"((r)[3]) : "r"(addr))
#define LDMX4T(r, addr) \
    asm volatile("ldmatrix.sync.aligned.m8n8.x4.trans.shared.b16 {%0,%1,%2,%3}, [%4];" \
        : "=r"((r)[0]), "=r"((r)[1]), "=r"((r)[2]), "=r"((r)[3]) : "r"(addr))

#define MMAF16(c, a, b) \
    asm volatile("mma.sync.aligned.m16n8k16.row.col.f32.f16.f16.f32 " \
        "{%0,%1,%2,%3}, {%4,%5,%6,%7}, {%8,%9}, {%0,%1,%2,%3};" \
        : "+f"((c)[0]), "+f"((c)[1]), "+f"((c)[2]), "+f"((c)[3]) \
        : "r"((a)[0]), "r"((a)[1]), "r"((a)[2]), "r"((a)[3]), "r"((b)[0]), "r"((b)[1]))

// ---------------- fp32 -> fp16 single convert (x) -----------------------------
__global__ void tofp16_kernel(const float* __restrict__ src,
                              __half* __restrict__ dst, int n4) {
    int i = blockIdx.x * blockDim.x + threadIdx.x;
    if (i >= n4) return;
    float4 v = ((const float4*)src)[i];
    ((__half2*)dst)[2*i]   = __floats2half2_rn(v.x, v.y);
    ((__half2*)dst)[2*i+1] = __floats2half2_rn(v.z, v.w);
}

// ---- fused 4-matrix W split to fp16 hi/lo (one launch) ----
__global__ void split_w_kernel(const float* __restrict__ w0, const float* __restrict__ w1,
                               const float* __restrict__ w2, const float* __restrict__ w3) {
    const float* srcs[4] = {w0, w1, w2, w3};
    int m = blockIdx.y;
    const float* src = srcs[m];
    __half* hi = g_wh[m];
    __half* lo = g_wl[m];
    int i = blockIdx.x * blockDim.x + threadIdx.x;
    float4 v = ((const float4*)src)[i];
    float vs[4] = {v.x, v.y, v.z, v.w};
    __half h[4], l[4];
    #pragma unroll
    for (int j = 0; j < 4; j++) {
        h[j] = __float2half(vs[j]);
        l[j] = __float2half(vs[j] - __half2float(h[j]));
    }
    __half2 h0; h0.x = h[0]; h0.y = h[1];
    __half2 h1; h1.x = h[2]; h1.y = h[3];
    __half2 l0; l0.x = l[0]; l0.y = l[1];
    __half2 l1; l1.x = l[2]; l1.y = l[3];
    ((__half2*)hi)[2*i]   = h0;
    ((__half2*)hi)[2*i+1] = h1;
    ((__half2*)lo)[2*i]   = l0;
    ((__half2*)lo)[2*i+1] = l1;
}

// ---------------- RoPE table -------------------------------------------------
__global__ void rope_table_kernel() {
    int i = blockIdx.x * blockDim.x + threadIdx.x;
    if (i >= TSEQ * 64) return;
    int t = i >> 6, d = i & 63;
    double inv = exp(-((double)(2 * d) / 128.0) * log(10000.0));
    double ang = (double)t * inv;
    double s, c;
    sincos(ang, &s, &c);
    g_cos[i] = (float)c;
    g_sin[i] = (float)s;
}

// ================= warp-mma fp16 2-pass GEMM (occ=2, 2-stage BK32) ===========
// C = A*Bh + A*Bl (A single fp16, B hi/lo).
// MODE 0: C fp32 [M,2048]. MODE 1: fused QKV with RoPE epilogue writing
//         q/k/v single fp16 into flash layout.
#define ROWB 80
#define PART (128 * ROWB)          // 10240
#define STG  (3 * PART)            // 30720 per stage
#define NSTG 2
#define TILEPAD 130
#define GEMM_SMEM 66560            // max(2*STG, 128*130*4)

template<int MODE>
__global__ void __launch_bounds__(256, 2)
tc_gemm_kernel(const __half* __restrict__ A,
               const __half* __restrict__ Bhi, const __half* __restrict__ Blo,
               float* __restrict__ C0)
{
    extern __shared__ char smem[];
    const uint32_t sb = smem_u32(smem);
    const int tid = threadIdx.x;
    const int lane = tid & 31, w = tid >> 5;
    const int wm = w & 1, wn = w >> 1;

    const __half* aP = A   + (size_t)blockIdx.y * 128 * HMODEL;
    const __half* bH = Bhi + (size_t)blockIdx.x * 128 * HMODEL;
    const __half* bL = Blo + (size_t)blockIdx.x * 128 * HMODEL;

    const int c0 = tid, c1 = tid + 256;
    const int r0 = c0 >> 2, q0 = c0 & 3;
    const int r1 = c1 >> 2, q1 = c1 & 3;

    auto load_stage = [&](int s, int kc) {
        uint32_t base = sb + s * STG;
        size_t g0 = (size_t)r0 * HMODEL + kc * 32 + q0 * 8;
        size_t g1 = (size_t)r1 * HMODEL + kc * 32 + q1 * 8;
        uint32_t d0 = base + r0 * ROWB + q0 * 16;
        uint32_t d1 = base + r1 * ROWB + q1 * 16;
        cp16(d0,            aP + g0);  cp16(d1,            aP + g1);
        cp16(d0 + PART,     bH + g0);  cp16(d1 + PART,     bH + g1);
        cp16(d0 + 2*PART,   bL + g0);  cp16(d1 + 2*PART,   bL + g1);
    };

    float acc[4][4][4];
    #pragma unroll
    for (int i = 0; i < 4; i++)
        #pragma unroll
        for (int j = 0; j < 4; j++)
            #pragma unroll
            for (int e = 0; e < 4; e++) acc[i][j][e] = 0.f;

    load_stage(0, 0); CP_COMMIT();
    load_stage(1, 1); CP_COMMIT();

    const int NKC = HMODEL / 32;   // 64
    for (int kc = 0; kc < NKC; kc++) {
        CP_WAIT(1);
        __syncthreads();
        uint32_t stage = sb + (kc & 1) * STG;

        #pragma unroll
        for (int step = 0; step < 2; step++) {
            uint32_t bhi[4][2], blo[4][2];
            const int qd = lane >> 3;
            #pragma unroll
            for (int nt2 = 0; nt2 < 2; nt2++) {
                uint32_t brow = wn * 32 + nt2 * 16 + (qd >> 1) * 8 + (lane & 7);
                uint32_t bd = stage + PART + brow * ROWB + step * 32 + (qd & 1) * 16;
                uint32_t th[4], tl[4];
                LDMX4(th, bd);
                LDMX4(tl, bd + PART);
                bhi[nt2*2][0] = th[0]; bhi[nt2*2][1] = th[1];
                bhi[nt2*2+1][0] = th[2]; bhi[nt2*2+1][1] = th[3];
                blo[nt2*2][0] = tl[0]; blo[nt2*2][1] = tl[1];
                blo[nt2*2+1][0] = tl[2]; blo[nt2*2+1][1] = tl[3];
            }
            #pragma unroll
            for (int mt = 0; mt < 4; mt++) {
                uint32_t ah[4];
                uint32_t arow = wm * 64 + mt * 16 + (lane & 15);
                uint32_t ad = stage + arow * ROWB + step * 32 + (lane >> 4) * 16;
                LDMX4(ah, ad);
                #pragma unroll
                for (int nt = 0; nt < 4; nt++) MMAF16(acc[mt][nt], ah, bhi[nt]);
                #pragma unroll
                for (int nt = 0; nt < 4; nt++) MMAF16(acc[mt][nt], ah, blo[nt]);
            }
        }
        __syncthreads();
        if (kc + 2 < NKC) load_stage(kc & 1, kc + 2);
        CP_COMMIT();
    }

    if (MODE == 0) {
        #pragma unroll
        for (int mt = 0; mt < 4; mt++) {
            int mrow = blockIdx.y * 128 + wm * 64 + mt * 16 + (lane >> 2);
            #pragma unroll
            for (int nt = 0; nt < 4; nt++) {
                int n = blockIdx.x * 128 + wn * 32 + nt * 8 + (lane & 3) * 2;
                float* dst = C0 + (size_t)mrow * HMODEL + n;
                *(float2*)dst = make_float2(acc[mt][nt][0], acc[mt][nt][1]);
                *(float2*)(dst + 8 * HMODEL) = make_float2(acc[mt][nt][2], acc[mt][nt][3]);
            }
        }
    } else {
        float* tile = (float*)smem;   // [128][TILEPAD]
        #pragma unroll
        for (int mt = 0; mt < 4; mt++) {
            int rl = wm * 64 + mt * 16 + (lane >> 2);
            #pragma unroll
            for (int nt = 0; nt < 4; nt++) {
                int cl = wn * 32 + nt * 8 + (lane & 3) * 2;
                tile[rl * TILEPAD + cl]       = acc[mt][nt][0];
                tile[rl * TILEPAD + cl + 1]   = acc[mt][nt][1];
                tile[(rl + 8) * TILEPAD + cl]     = acc[mt][nt][2];
                tile[(rl + 8) * TILEPAD + cl + 1] = acc[mt][nt][3];
            }
        }
        __syncthreads();

        const int matrix = blockIdx.x >> 4;     // 0:q 1:k 2:v
        const int head   = blockIdx.x & 15;
        __half* hi = (matrix == 0) ? g_qh : (matrix == 1) ? g_kh : g_vh;
        const bool dorope = (matrix < 2);

        #pragma unroll
        for (int it = 0; it < 16; it++) {
            int idx = tid + it * 256;
            int rl = idx >> 5;
            int dp = (idx & 31) * 2;
            int mrow = blockIdx.y * 128 + rl;
            int b = mrow >> 11, t = mrow & (TSEQ - 1);
            float x0a = tile[rl * TILEPAD + dp];
            float x0b = tile[rl * TILEPAD + dp + 1];
            float x1a = tile[rl * TILEPAD + dp + 64];
            float x1b = tile[rl * TILEPAD + dp + 65];
            float y0a, y0b, y1a, y1b;
            if (dorope) {
                float c0 = g_cos[t * 64 + dp],     s0 = g_sin[t * 64 + dp];
                float c1 = g_cos[t * 64 + dp + 1], s1 = g_sin[t * 64 + dp + 1];
                y0a = x0a * c0 - x1a * s0;  y1a = x1a * c0 + x0a * s0;
                y0b = x0b * c1 - x1b * s1;  y1b = x1b * c1 + x0b * s1;
            } else {
                y0a = x0a; y0b = x0b; y1a = x1a; y1b = x1b;
            }
            size_t base = ((size_t)(b * NHEADS + head) * TSEQ + t) * HDIM;
            *(__half2*)(hi + base + dp)      = __floats2half2_rn(y0a, y0b);
            *(__half2*)(hi + base + dp + 64) = __floats2half2_rn(y1a, y1b);
        }
    }
}

// ================= mma.sync causal flash attention (fp16 1-pass) =============
// Q, K, V all single fp16. S = Q*K; O += P*V.
#define FROWE 136
#define FROWB (FROWE * 2)
#define FQ_PART (128 * FROWB)        // 34816
#define FKV_PART (64 * FROWB)        // 17408
#define FSTAGE (2 * FKV_PART)        // 34816 (k, v)
#define FSTAGE_OFF FQ_PART
#define FLASH_SMEM (FSTAGE_OFF + 2 * FSTAGE)   // 104448

__global__ void __launch_bounds__(256, 1) flash_mma_kernel(__half* __restrict__ outh)
{
    extern __shared__ char fsm[];
    const uint32_t sb = smem_u32(fsm);
    const int qb = (gridDim.x - 1) - blockIdx.x;   // longest work first
    const int h = blockIdx.y, b = blockIdx.z;
    const int tid = threadIdx.x, lane = tid & 31, w = tid >> 5;

    const size_t headoff = ((size_t)(b * NHEADS + h) * TSEQ) * HDIM;
    const __half* qp = g_qh + headoff + (size_t)qb * 128 * HDIM;
    const __half* kp = g_kh + headoff;
    const __half* vp = g_vh + headoff;

    // ---- load Q: 2048 x 16B chunks ----
    #pragma unroll
    for (int t = 0; t < 8; t++) {
        int cid = tid + t * 256;
        int r = cid >> 4, cq = cid & 15;
        cp16(sb + r * FROWB + cq * 16, qp + (size_t)r * HDIM + cq * 8);
    }

    auto load_kv = [&](int j, int stage) {
        uint32_t base = sb + FSTAGE_OFF + stage * FSTAGE;
        const __half* srcs[2] = {
            kp + (size_t)j * 64 * HDIM, vp + (size_t)j * 64 * HDIM };
        #pragma unroll
        for (int t = 0; t < 8; t++) {
            int cid = tid + t * 256;
            int part = cid >> 10;
            int pc = cid & 1023;
            int r = pc >> 4, cq = pc & 15;
            cp16(base + part * FKV_PART + r * FROWB + cq * 16,
                 srcs[part] + (size_t)r * HDIM + cq * 8);
        }
    };

    const int nj = 2 * qb + 2;
    load_kv(0, 0); CP_COMMIT();
    load_kv(1, 1); CP_COMMIT();

    float oacc[16][4];
    #pragma unroll
    for (int i = 0; i < 16; i++)
        #pragma unroll
        for (int e = 0; e < 4; e++) oacc[i][e] = 0.f;
    float m_s[2] = {-1e30f, -1e30f};
    float l_s[2] = {0.f, 0.f};
    const float scale = 0.08838834764831845f;

    for (int j = 0; j < nj; j++) {
        CP_WAIT(1);
        __syncthreads();
        uint32_t stg = sb + FSTAGE_OFF + (j & 1) * FSTAGE;

        float sacc[8][4];
        #pragma unroll
        for (int i = 0; i < 8; i++)
            #pragma unroll
            for (int e = 0; e < 4; e++) sacc[i][e] = 0.f;

        const int qd = lane >> 3;
        #pragma unroll
        for (int kc = 0; kc < 8; kc++) {
            uint32_t ah[4];
            uint32_t arow = w * 16 + (lane & 15);
            uint32_t aad = sb + arow * FROWB + kc * 32 + (lane >> 4) * 16;
            LDMX4(ah, aad);
            #pragma unroll
            for (int nt2 = 0; nt2 < 4; nt2++) {
                uint32_t brow = nt2 * 16 + (qd >> 1) * 8 + (lane & 7);
                uint32_t bad = stg + brow * FROWB + kc * 32 + (qd & 1) * 16;
                uint32_t bh4[4];
                LDMX4(bh4, bad);
                uint32_t b0[2] = {bh4[0], bh4[1]}, b1[2] = {bh4[2], bh4[3]};
                MMAF16(sacc[nt2*2],   ah, b0);
                MMAF16(sacc[nt2*2+1], ah, b1);
            }
        }

        const bool need_mask = (j >= 2 * qb);
        const int rowg0 = qb * 128 + w * 16 + (lane >> 2);
        const int colb = j * 64 + (lane & 3) * 2;
        #pragma unroll
        for (int half = 0; half < 2; half++) {
            int rowg = rowg0 + half * 8;
            float mloc = -1e30f;
            #pragma unroll
            for (int nt = 0; nt < 8; nt++) {
                float v0 = sacc[nt][half*2]     * scale;
                float v1 = sacc[nt][half*2 + 1] * scale;
                if (need_mask) {
                    if (colb + nt * 8     > rowg) v0 = -1e30f;
                    if (colb + nt * 8 + 1 > rowg) v1 = -1e30f;
                }
                sacc[nt][half*2]     = v0;
                sacc[nt][half*2 + 1] = v1;
                mloc = fmaxf(mloc, fmaxf(v0, v1));
            }
            mloc = fmaxf(mloc, __shfl_xor_sync(0xffffffffu, mloc, 1));
            mloc = fmaxf(mloc, __shfl_xor_sync(0xffffffffu, mloc, 2));
            float mn = fmaxf(m_s[half], mloc);
            float corr = __expf(m_s[half] - mn);
            m_s[half] = mn;
            float rsum = 0.f;
            #pragma unroll
            for (int nt = 0; nt < 8; nt++) {
                float p0 = __expf(sacc[nt][half*2]     - mn);
                float p1 = __expf(sacc[nt][half*2 + 1] - mn);
                sacc[nt][half*2]     = p0;
                sacc[nt][half*2 + 1] = p1;
                rsum += p0 + p1;
            }
            rsum += __shfl_xor_sync(0xffffffffu, rsum, 1);
            rsum += __shfl_xor_sync(0xffffffffu, rsum, 2);
            l_s[half] = l_s[half] * corr + rsum;
            #pragma unroll
            for (int nt = 0; nt < 16; nt++) {
                oacc[nt][half*2]     *= corr;
                oacc[nt][half*2 + 1] *= corr;
            }
        }

        #pragma unroll
        for (int kc2 = 0; kc2 < 4; kc2++) {
            uint32_t pf[4];
            #pragma unroll
            for (int e = 0; e < 4; e++) {
                int nt = 2 * kc2 + (e >> 1);
                int co = (e & 1) * 2;
                asm("cvt.rn.f16x2.f32 %0, %1, %2;"
                    : "=r"(pf[e]) : "f"(sacc[nt][co + 1]), "f"(sacc[nt][co]));
            }
            #pragma unroll
            for (int nt8 = 0; nt8 < 8; nt8++) {
                uint32_t vrow = kc2 * 16 + (qd & 1) * 8 + (lane & 7);
                uint32_t vad = stg + FKV_PART + vrow * FROWB + nt8 * 32 + (qd >> 1) * 16;
                uint32_t vh4[4];
                LDMX4T(vh4, vad);
                uint32_t v0[2] = {vh4[0], vh4[1]}, v1[2] = {vh4[2], vh4[3]};
                MMAF16(oacc[nt8*2],   pf, v0);
                MMAF16(oacc[nt8*2+1], pf, v1);
            }
        }

        __syncthreads();
        if (j + 2 < nj) load_kv(j + 2, j & 1);
        CP_COMMIT();
    }

    // ---- epilogue: normalize, write fp16 single [B,T,H] ----
    #pragma unroll
    for (int half = 0; half < 2; half++) {
        float inv = 1.0f / l_s[half];
        int t = qb * 128 + w * 16 + (lane >> 2) + half * 8;
        size_t rowoff = (((size_t)(b * TSEQ + t) * NHEADS + h) * HDIM);
        #pragma unroll
        for (int nt = 0; nt < 16; nt++) {
            int d = nt * 8 + (lane & 3) * 2;
            float y0 = oacc[nt][half*2] * inv;
            float y1 = oacc[nt][half*2 + 1] * inv;
            *(__half2*)(outh + rowoff + d) = __floats2half2_rn(y0, y1);
        }
    }
}

// ---------------- launch -----------------------------------------------------
extern "C" void kernel_launch(void* const* d_in, const int* in_sizes, int n_in,
                              void* d_out, int out_size) {
    const float* x  = (const float*)d_in[0];
    const float* Wq = (const float*)d_in[1];
    const float* Wk = (const float*)d_in[2];
    const float* Wv = (const float*)d_in[3];
    const float* Wo = (const float*)d_in[4];
    float* out = (float*)d_out;

    __half *xh, *wh, *wl, *aoh;
    cudaGetSymbolAddress((void**)&xh,  g_xh);
    cudaGetSymbolAddress((void**)&wh,  g_wh);
    cudaGetSymbolAddress((void**)&wl,  g_wl);
    cudaGetSymbolAddress((void**)&aoh, g_aoh);

    cudaFuncSetAttribute(tc_gemm_kernel<0>,
                         cudaFuncAttributeMaxDynamicSharedMemorySize, GEMM_SMEM);
    cudaFuncSetAttribute(tc_gemm_kernel<1>,
                         cudaFuncAttributeMaxDynamicSharedMemorySize, GEMM_SMEM);
    cudaFuncSetAttribute(flash_mma_kernel,
                         cudaFuncAttributeMaxDynamicSharedMemorySize, FLASH_SMEM);

    rope_table_kernel<<<(TSEQ * 64 + 255) / 256, 256>>>();

    const int NX4 = MROWS * HMODEL / 4;
    const int NW4 = HMODEL * HMODEL / 4;
    const size_t WSTRIDE = (size_t)HMODEL * HMODEL;
    tofp16_kernel<<<(NX4 + 255) / 256, 256>>>(x, xh, NX4);
    split_w_kernel<<<dim3(NW4 / 256, 4), 256>>>(Wq, Wk, Wv, Wo);

    dim3 qkvgrid(3 * HMODEL / 128, MROWS / 128);   // (48, 64)
    tc_gemm_kernel<1><<<qkvgrid, 256, GEMM_SMEM>>>(xh, wh, wl, nullptr);

    flash_mma_kernel<<<dim3(TSEQ / 128, NHEADS, BATCH), 256, FLASH_SMEM>>>(aoh);

    dim3 ogrid(HMODEL / 128, MROWS / 128);   // (16, 64)
    tc_gemm_kernel<0><<<ogrid, 256, GEMM_SMEM>>>(aoh, wh + 3 * WSTRIDE, wl + 3 * WSTRIDE, out);
}

// round 15
// speedup vs baseline: 2.8409x; 1.5493x over previous
#include <cuda_runtime.h>
#include <cuda_bf16.h>
#include <cuda_fp16.h>
#include <math.h>
#include <stdint.h>

#define NHEADS 16
#define HDIM 128
#define TSEQ 2048
#define BATCH 4
#define HMODEL 2048
#define MROWS (BATCH*TSEQ)   // 8192

// ---------------- scratch (device globals: allocation-free) ----------------
__device__ float g_cos[TSEQ*64];
__device__ float g_sin[TSEQ*64];
// fp16 operands for projection GEMMs (all single fp16, 1-pass)
__device__ __half g_xh[(size_t)MROWS*HMODEL];
__device__ __half g_wh[4][(size_t)HMODEL*HMODEL];   // q,k,v,o contiguous
__device__ __half g_aoh[(size_t)MROWS*HMODEL];
// fp16 q/k/v single for flash (post-RoPE), written by QKV GEMM epilogue
__device__ __half g_qh[(size_t)BATCH*NHEADS*TSEQ*HDIM];
__device__ __half g_kh[(size_t)BATCH*NHEADS*TSEQ*HDIM];
__device__ __half g_vh[(size_t)BATCH*NHEADS*TSEQ*HDIM];

// ================= PTX helpers (baseline ISA only) ==========================
__device__ __forceinline__ uint32_t smem_u32(const void* p) {
    uint32_t a;
    asm("{ .reg .u64 t; cvta.to.shared.u64 t, %1; cvt.u32.u64 %0, t; }" : "=r"(a) : "l"(p));
    return a;
}
__device__ __forceinline__ void cp16(uint32_t dst, const void* src) {
    asm volatile("cp.async.cg.shared.global [%0], [%1], 16;" :: "r"(dst), "l"(src));
}
#define CP_COMMIT() asm volatile("cp.async.commit_group;" ::: "memory")
#define CP_WAIT(n)  asm volatile("cp.async.wait_group %0;" :: "n"(n) : "memory")

#define LDMX4(r, addr) \
    asm volatile("ldmatrix.sync.aligned.m8n8.x4.shared.b16 {%0,%1,%2,%3}, [%4];" \
        : "=r"((r)[0]), "=r"((r)[1]), "=r"((r)[2]), "=r"((r)[3]) : "r"(addr))
#define LDMX4T(r, addr) \
    asm volatile("ldmatrix.sync.aligned.m8n8.x4.trans.shared.b16 {%0,%1,%2,%3}, [%4];" \
        : "=r"((r)[0]), "=r"((r)[1]), "=r"((r)[2]), "=r"((r)[3]) : "r"(addr))

#define MMAF16(c, a, b) \
    asm volatile("mma.sync.aligned.m16n8k16.row.col.f32.f16.f16.f32 " \
        "{%0,%1,%2,%3}, {%4,%5,%6,%7}, {%8,%9}, {%0,%1,%2,%3};" \
        : "+f"((c)[0]), "+f"((c)[1]), "+f"((c)[2]), "+f"((c)[3]) \
        : "r"((a)[0]), "r"((a)[1]), "r"((a)[2]), "r"((a)[3]), "r"((b)[0]), "r"((b)[1]))

// ---------------- fp32 -> fp16 convert (x) ------------------------------------
__global__ void tofp16_kernel(const float* __restrict__ src,
                              __half* __restrict__ dst, int n4) {
    int i = blockIdx.x * blockDim.x + threadIdx.x;
    if (i >= n4) return;
    float4 v = ((const float4*)src)[i];
    ((__half2*)dst)[2*i]   = __floats2half2_rn(v.x, v.y);
    ((__half2*)dst)[2*i+1] = __floats2half2_rn(v.z, v.w);
}

// ---- fused 4-matrix W convert to fp16 (one launch) ----
__global__ void conv_w_kernel(const float* __restrict__ w0, const float* __restrict__ w1,
                              const float* __restrict__ w2, const float* __restrict__ w3) {
    const float* srcs[4] = {w0, w1, w2, w3};
    int m = blockIdx.y;
    const float* src = srcs[m];
    __half* hi = g_wh[m];
    int i = blockIdx.x * blockDim.x + threadIdx.x;
    float4 v = ((const float4*)src)[i];
    ((__half2*)hi)[2*i]   = __floats2half2_rn(v.x, v.y);
    ((__half2*)hi)[2*i+1] = __floats2half2_rn(v.z, v.w);
}

// ---------------- RoPE table -------------------------------------------------
__global__ void rope_table_kernel() {
    int i = blockIdx.x * blockDim.x + threadIdx.x;
    if (i >= TSEQ * 64) return;
    int t = i >> 6, d = i & 63;
    double inv = exp(-((double)(2 * d) / 128.0) * log(10000.0));
    double ang = (double)t * inv;
    double s, c;
    sincos(ang, &s, &c);
    g_cos[i] = (float)c;
    g_sin[i] = (float)s;
}

// ================= warp-mma fp16 1-pass GEMM (occ=2, 2-stage BK32) ===========
// C = A*B (both single fp16).
// MODE 0: C fp32 [M,2048]. MODE 1: fused QKV with RoPE epilogue writing
//         q/k/v single fp16 into flash layout.
#define ROWB 80
#define PART (128 * ROWB)          // 10240
#define STG  (2 * PART)            // 20480 per stage (A, B)
#define TILEPAD 130
#define GEMM_SMEM 66560            // max(2*STG=40960, 128*130*4=66560)

template<int MODE>
__global__ void __launch_bounds__(256, 2)
tc_gemm_kernel(const __half* __restrict__ A, const __half* __restrict__ B,
               float* __restrict__ C0)
{
    extern __shared__ char smem[];
    const uint32_t sb = smem_u32(smem);
    const int tid = threadIdx.x;
    const int lane = tid & 31, w = tid >> 5;
    const int wm = w & 1, wn = w >> 1;

    const __half* aP = A + (size_t)blockIdx.y * 128 * HMODEL;
    const __half* bP = B + (size_t)blockIdx.x * 128 * HMODEL;

    const int c0 = tid, c1 = tid + 256;
    const int r0 = c0 >> 2, q0 = c0 & 3;
    const int r1 = c1 >> 2, q1 = c1 & 3;

    auto load_stage = [&](int s, int kc) {
        uint32_t base = sb + s * STG;
        size_t g0 = (size_t)r0 * HMODEL + kc * 32 + q0 * 8;
        size_t g1 = (size_t)r1 * HMODEL + kc * 32 + q1 * 8;
        uint32_t d0 = base + r0 * ROWB + q0 * 16;
        uint32_t d1 = base + r1 * ROWB + q1 * 16;
        cp16(d0,        aP + g0);  cp16(d1,        aP + g1);
        cp16(d0 + PART, bP + g0);  cp16(d1 + PART, bP + g1);
    };

    float acc[4][4][4];
    #pragma unroll
    for (int i = 0; i < 4; i++)
        #pragma unroll
        for (int j = 0; j < 4; j++)
            #pragma unroll
            for (int e = 0; e < 4; e++) acc[i][j][e] = 0.f;

    load_stage(0, 0); CP_COMMIT();
    load_stage(1, 1); CP_COMMIT();

    const int NKC = HMODEL / 32;   // 64
    for (int kc = 0; kc < NKC; kc++) {
        CP_WAIT(1);
        __syncthreads();
        uint32_t stage = sb + (kc & 1) * STG;

        #pragma unroll
        for (int step = 0; step < 2; step++) {
            uint32_t bf[4][2];
            const int qd = lane >> 3;
            #pragma unroll
            for (int nt2 = 0; nt2 < 2; nt2++) {
                uint32_t brow = wn * 32 + nt2 * 16 + (qd >> 1) * 8 + (lane & 7);
                uint32_t bd = stage + PART + brow * ROWB + step * 32 + (qd & 1) * 16;
                uint32_t th[4];
                LDMX4(th, bd);
                bf[nt2*2][0] = th[0]; bf[nt2*2][1] = th[1];
                bf[nt2*2+1][0] = th[2]; bf[nt2*2+1][1] = th[3];
            }
            #pragma unroll
            for (int mt = 0; mt < 4; mt++) {
                uint32_t ah[4];
                uint32_t arow = wm * 64 + mt * 16 + (lane & 15);
                uint32_t ad = stage + arow * ROWB + step * 32 + (lane >> 4) * 16;
                LDMX4(ah, ad);
                #pragma unroll
                for (int nt = 0; nt < 4; nt++) MMAF16(acc[mt][nt], ah, bf[nt]);
            }
        }
        __syncthreads();
        if (kc + 2 < NKC) load_stage(kc & 1, kc + 2);
        CP_COMMIT();
    }

    if (MODE == 0) {
        #pragma unroll
        for (int mt = 0; mt < 4; mt++) {
            int mrow = blockIdx.y * 128 + wm * 64 + mt * 16 + (lane >> 2);
            #pragma unroll
            for (int nt = 0; nt < 4; nt++) {
                int n = blockIdx.x * 128 + wn * 32 + nt * 8 + (lane & 3) * 2;
                float* dst = C0 + (size_t)mrow * HMODEL + n;
                *(float2*)dst = make_float2(acc[mt][nt][0], acc[mt][nt][1]);
                *(float2*)(dst + 8 * HMODEL) = make_float2(acc[mt][nt][2], acc[mt][nt][3]);
            }
        }
    } else {
        float* tile = (float*)smem;   // [128][TILEPAD]
        #pragma unroll
        for (int mt = 0; mt < 4; mt++) {
            int rl = wm * 64 + mt * 16 + (lane >> 2);
            #pragma unroll
            for (int nt = 0; nt < 4; nt++) {
                int cl = wn * 32 + nt * 8 + (lane & 3) * 2;
                tile[rl * TILEPAD + cl]       = acc[mt][nt][0];
                tile[rl * TILEPAD + cl + 1]   = acc[mt][nt][1];
                tile[(rl + 8) * TILEPAD + cl]     = acc[mt][nt][2];
                tile[(rl + 8) * TILEPAD + cl + 1] = acc[mt][nt][3];
            }
        }
        __syncthreads();

        const int matrix = blockIdx.x >> 4;     // 0:q 1:k 2:v
        const int head   = blockIdx.x & 15;
        __half* hi = (matrix == 0) ? g_qh : (matrix == 1) ? g_kh : g_vh;
        const bool dorope = (matrix < 2);

        #pragma unroll
        for (int it = 0; it < 16; it++) {
            int idx = tid + it * 256;
            int rl = idx >> 5;
            int dp = (idx & 31) * 2;
            int mrow = blockIdx.y * 128 + rl;
            int b = mrow >> 11, t = mrow & (TSEQ - 1);
            float x0a = tile[rl * TILEPAD + dp];
            float x0b = tile[rl * TILEPAD + dp + 1];
            float x1a = tile[rl * TILEPAD + dp + 64];
            float x1b = tile[rl * TILEPAD + dp + 65];
            float y0a, y0b, y1a, y1b;
            if (dorope) {
                float c0 = g_cos[t * 64 + dp],     s0 = g_sin[t * 64 + dp];
                float c1 = g_cos[t * 64 + dp + 1], s1 = g_sin[t * 64 + dp + 1];
                y0a = x0a * c0 - x1a * s0;  y1a = x1a * c0 + x0a * s0;
                y0b = x0b * c1 - x1b * s1;  y1b = x1b * c1 + x0b * s1;
            } else {
                y0a = x0a; y0b = x0b; y1a = x1a; y1b = x1b;
            }
            size_t base = ((size_t)(b * NHEADS + head) * TSEQ + t) * HDIM;
            *(__half2*)(hi + base + dp)      = __floats2half2_rn(y0a, y0b);
            *(__half2*)(hi + base + dp + 64) = __floats2half2_rn(y1a, y1b);
        }
    }
}

// ================= mma.sync causal flash attention (fp16 1-pass) =============
#define FROWE 136
#define FROWB (FROWE * 2)
#define FQ_PART (128 * FROWB)        // 34816
#define FKV_PART (64 * FROWB)        // 17408
#define FSTAGE (2 * FKV_PART)        // 34816 (k, v)
#define FSTAGE_OFF FQ_PART
#define FLASH_SMEM (FSTAGE_OFF + 2 * FSTAGE)   // 104448

__global__ void __launch_bounds__(256, 1) flash_mma_kernel(__half* __restrict__ outh)
{
    extern __shared__ char fsm[];
    const uint32_t sb = smem_u32(fsm);
    const int qb = (gridDim.x - 1) - blockIdx.x;   // longest work first
    const int h = blockIdx.y, b = blockIdx.z;
    const int tid = threadIdx.x, lane = tid & 31, w = tid >> 5;

    const size_t headoff = ((size_t)(b * NHEADS + h) * TSEQ) * HDIM;
    const __half* qp = g_qh + headoff + (size_t)qb * 128 * HDIM;
    const __half* kp = g_kh + headoff;
    const __half* vp = g_vh + headoff;

    #pragma unroll
    for (int t = 0; t < 8; t++) {
        int cid = tid + t * 256;
        int r = cid >> 4, cq = cid & 15;
        cp16(sb + r * FROWB + cq * 16, qp + (size_t)r * HDIM + cq * 8);
    }

    auto load_kv = [&](int j, int stage) {
        uint32_t base = sb + FSTAGE_OFF + stage * FSTAGE;
        const __half* srcs[2] = {
            kp + (size_t)j * 64 * HDIM, vp + (size_t)j * 64 * HDIM };
        #pragma unroll
        for (int t = 0; t < 8; t++) {
            int cid = tid + t * 256;
            int part = cid >> 10;
            int pc = cid & 1023;
            int r = pc >> 4, cq = pc & 15;
            cp16(base + part * FKV_PART + r * FROWB + cq * 16,
                 srcs[part] + (size_t)r * HDIM + cq * 8);
        }
    };

    const int nj = 2 * qb + 2;
    load_kv(0, 0); CP_COMMIT();
    load_kv(1, 1); CP_COMMIT();

    float oacc[16][4];
    #pragma unroll
    for (int i = 0; i < 16; i++)
        #pragma unroll
        for (int e = 0; e < 4; e++) oacc[i][e] = 0.f;
    float m_s[2] = {-1e30f, -1e30f};
    float l_s[2] = {0.f, 0.f};
    const float scale = 0.08838834764831845f;

    for (int j = 0; j < nj; j++) {
        CP_WAIT(1);
        __syncthreads();
        uint32_t stg = sb + FSTAGE_OFF + (j & 1) * FSTAGE;

        float sacc[8][4];
        #pragma unroll
        for (int i = 0; i < 8; i++)
            #pragma unroll
            for (int e = 0; e < 4; e++) sacc[i][e] = 0.f;

        const int qd = lane >> 3;
        #pragma unroll
        for (int kc = 0; kc < 8; kc++) {
            uint32_t ah[4];
            uint32_t arow = w * 16 + (lane & 15);
            uint32_t aad = sb + arow * FROWB + kc * 32 + (lane >> 4) * 16;
            LDMX4(ah, aad);
            #pragma unroll
            for (int nt2 = 0; nt2 < 4; nt2++) {
                uint32_t brow = nt2 * 16 + (qd >> 1) * 8 + (lane & 7);
                uint32_t bad = stg + brow * FROWB + kc * 32 + (qd & 1) * 16;
                uint32_t bh4[4];
                LDMX4(bh4, bad);
                uint32_t b0[2] = {bh4[0], bh4[1]}, b1[2] = {bh4[2], bh4[3]};
                MMAF16(sacc[nt2*2],   ah, b0);
                MMAF16(sacc[nt2*2+1], ah, b1);
            }
        }

        const bool need_mask = (j >= 2 * qb);
        const int rowg0 = qb * 128 + w * 16 + (lane >> 2);
        const int colb = j * 64 + (lane & 3) * 2;
        #pragma unroll
        for (int half = 0; half < 2; half++) {
            int rowg = rowg0 + half * 8;
            float mloc = -1e30f;
            #pragma unroll
            for (int nt = 0; nt < 8; nt++) {
                float v0 = sacc[nt][half*2]     * scale;
                float v1 = sacc[nt][half*2 + 1] * scale;
                if (need_mask) {
                    if (colb + nt * 8     > rowg) v0 = -1e30f;
                    if (colb + nt * 8 + 1 > rowg) v1 = -1e30f;
                }
                sacc[nt][half*2]     = v0;
                sacc[nt][half*2 + 1] = v1;
                mloc = fmaxf(mloc, fmaxf(v0, v1));
            }
            mloc = fmaxf(mloc, __shfl_xor_sync(0xffffffffu, mloc, 1));
            mloc = fmaxf(mloc, __shfl_xor_sync(0xffffffffu, mloc, 2));
            float mn = fmaxf(m_s[half], mloc);
            float corr = __expf(m_s[half] - mn);
            m_s[half] = mn;
            float rsum = 0.f;
            #pragma unroll
            for (int nt = 0; nt < 8; nt++) {
                float p0 = __expf(sacc[nt][half*2]     - mn);
                float p1 = __expf(sacc[nt][half*2 + 1] - mn);
                sacc[nt][half*2]     = p0;
                sacc[nt][half*2 + 1] = p1;
                rsum += p0 + p1;
            }
            rsum += __shfl_xor_sync(0xffffffffu, rsum, 1);
            rsum += __shfl_xor_sync(0xffffffffu, rsum, 2);
            l_s[half] = l_s[half] * corr + rsum;
            #pragma unroll
            for (int nt = 0; nt < 16; nt++) {
                oacc[nt][half*2]     *= corr;
                oacc[nt][half*2 + 1] *= corr;
            }
        }

        #pragma unroll
        for (int kc2 = 0; kc2 < 4; kc2++) {
            uint32_t pf[4];
            #pragma unroll
            for (int e = 0; e < 4; e++) {
                int nt = 2 * kc2 + (e >> 1);
                int co = (e & 1) * 2;
                asm("cvt.rn.f16x2.f32 %0, %1, %2;"
                    : "=r"(pf[e]) : "f"(sacc[nt][co + 1]), "f"(sacc[nt][co]));
            }
            #pragma unroll
            for (int nt8 = 0; nt8 < 8; nt8++) {
                uint32_t vrow = kc2 * 16 + (qd & 1) * 8 + (lane & 7);
                uint32_t vad = stg + FKV_PART + vrow * FROWB + nt8 * 32 + (qd >> 1) * 16;
                uint32_t vh4[4];
                LDMX4T(vh4, vad);
                uint32_t v0[2] = {vh4[0], vh4[1]}, v1[2] = {vh4[2], vh4[3]};
                MMAF16(oacc[nt8*2],   pf, v0);
                MMAF16(oacc[nt8*2+1], pf, v1);
            }
        }

        __syncthreads();
        if (j + 2 < nj) load_kv(j + 2, j & 1);
        CP_COMMIT();
    }

    #pragma unroll
    for (int half = 0; half < 2; half++) {
        float inv = 1.0f / l_s[half];
        int t = qb * 128 + w * 16 + (lane >> 2) + half * 8;
        size_t rowoff = (((size_t)(b * TSEQ + t) * NHEADS + h) * HDIM);
        #pragma unroll
        for (int nt = 0; nt < 16; nt++) {
            int d = nt * 8 + (lane & 3) * 2;
            float y0 = oacc[nt][half*2] * inv;
            float y1 = oacc[nt][half*2 + 1] * inv;
            *(__half2*)(outh + rowoff + d) = __floats2half2_rn(y0, y1);
        }
    }
}

// ---------------- launch -----------------------------------------------------
extern "C" void kernel_launch(void* const* d_in, const int* in_sizes, int n_in,
                              void* d_out, int out_size) {
    const float* x  = (const float*)d_in[0];
    const float* Wq = (const float*)d_in[1];
    const float* Wk = (const float*)d_in[2];
    const float* Wv = (const float*)d_in[3];
    const float* Wo = (const float*)d_in[4];
    float* out = (float*)d_out;

    __half *xh, *wh, *aoh;
    cudaGetSymbolAddress((void**)&xh,  g_xh);
    cudaGetSymbolAddress((void**)&wh,  g_wh);
    cudaGetSymbolAddress((void**)&aoh, g_aoh);

    cudaFuncSetAttribute(tc_gemm_kernel<0>,
                         cudaFuncAttributeMaxDynamicSharedMemorySize, GEMM_SMEM);
    cudaFuncSetAttribute(tc_gemm_kernel<1>,
                         cudaFuncAttributeMaxDynamicSharedMemorySize, GEMM_SMEM);
    cudaFuncSetAttribute(flash_mma_kernel,
                         cudaFuncAttributeMaxDynamicSharedMemorySize, FLASH_SMEM);

    rope_table_kernel<<<(TSEQ * 64 + 255) / 256, 256>>>();

    const int NX4 = MROWS * HMODEL / 4;
    const int NW4 = HMODEL * HMODEL / 4;
    const size_t WSTRIDE = (size_t)HMODEL * HMODEL;
    tofp16_kernel<<<(NX4 + 255) / 256, 256>>>(x, xh, NX4);
    conv_w_kernel<<<dim3(NW4 / 256, 4), 256>>>(Wq, Wk, Wv, Wo);

    dim3 qkvgrid(3 * HMODEL / 128, MROWS / 128);   // (48, 64)
    tc_gemm_kernel<1><<<qkvgrid, 256, GEMM_SMEM>>>(xh, wh, nullptr);

    flash_mma_kernel<<<dim3(TSEQ / 128, NHEADS, BATCH), 256, FLASH_SMEM>>>(aoh);

    dim3 ogrid(HMODEL / 128, MROWS / 128);   // (16, 64)
    tc_gemm_kernel<0><<<ogrid, 256, GEMM_SMEM>>>(aoh, wh + 3 * WSTRIDE, out);
}